// round 8
// baseline (speedup 1.0000x reference)
#include <cuda_runtime.h>
#include <cuda_fp16.h>
#include <cstdint>

#define BB 8
#define NN 2048
#define FIN 256
#define FOUT 64
#define LALPHA 0.2f
#define EBIAS 8.0f
#define SPLIT 32
#define SPLITK 4

// ---- scratch (device globals; no allocation) ----
__device__ float  g_WhL[BB * NN * FOUT];           // Wh*level fp32 (4 MB)
__device__ __half g_WhLh[BB * NN * FOUT];          // scaled fp16 (2 MB)
__device__ float  g_f1[BB * NN];
__device__ float  g_f2[BB * NN];
__device__ float  g_part[SPLIT * BB * NN];
__device__ __half g_expe[(size_t)BB * NN * NN];    // exp(e-8) fp16, masked->0 (67 MB)
__device__ float  g_pout[(size_t)SPLITK * BB * NN * FOUT];  // K-split partials (16 MB)

static __device__ __forceinline__ uint32_t smem_u32(const void* p) {
    return (uint32_t)__cvta_generic_to_shared(p);
}

// =====================================================================
// Kernel A: Wh = h@W, WhL = Wh*level, f1 = Wh@a1, f2 = Wh@a2
// =====================================================================
__global__ __launch_bounds__(256) void k_proj(const float* __restrict__ h,
                                              const float* __restrict__ W,
                                              const float* __restrict__ a,
                                              const float* __restrict__ level)
{
    __shared__ float sh_h[32 * FIN];
    __shared__ float red1[8][4][2];
    __shared__ float red2[8][4][2];

    const int t = threadIdx.x;
    const int row0 = blockIdx.x * 32;

    const float4* hg = (const float4*)(h + (size_t)row0 * FIN);
    float4* hs = (float4*)sh_h;
#pragma unroll
    for (int k = 0; k < 8; ++k) hs[t + k * 256] = hg[t + k * 256];
    __syncthreads();

    const int o = t & 63;
    const int g = t >> 6;
    const float a1o = a[o];
    const float a2o = a[FOUT + o];

    float acc[8] = {0.f, 0.f, 0.f, 0.f, 0.f, 0.f, 0.f, 0.f};

#pragma unroll 4
    for (int f4 = 0; f4 < FIN / 4; ++f4) {
        const float w0 = __ldg(&W[(f4 * 4 + 0) * FOUT + o]);
        const float w1 = __ldg(&W[(f4 * 4 + 1) * FOUT + o]);
        const float w2 = __ldg(&W[(f4 * 4 + 2) * FOUT + o]);
        const float w3 = __ldg(&W[(f4 * 4 + 3) * FOUT + o]);
#pragma unroll
        for (int rr = 0; rr < 8; ++rr) {
            const float4 hv = *(const float4*)&sh_h[(g * 8 + rr) * FIN + f4 * 4];
            acc[rr] = fmaf(hv.x, w0, acc[rr]);
            acc[rr] = fmaf(hv.y, w1, acc[rr]);
            acc[rr] = fmaf(hv.z, w2, acc[rr]);
            acc[rr] = fmaf(hv.w, w3, acc[rr]);
        }
    }

    const int lane = t & 31;
    const int half = (t >> 5) & 1;
#pragma unroll
    for (int rr = 0; rr < 8; ++rr) {
        const int row = row0 + g * 8 + rr;
        const float lev = __ldg(&level[row]);
        g_WhL[(size_t)row * FOUT + o] = acc[rr] * lev;
        float v1 = acc[rr] * a1o;
        float v2 = acc[rr] * a2o;
#pragma unroll
        for (int off = 16; off; off >>= 1) {
            v1 += __shfl_down_sync(0xffffffffu, v1, off);
            v2 += __shfl_down_sync(0xffffffffu, v2, off);
        }
        if (lane == 0) { red1[rr][g][half] = v1; red2[rr][g][half] = v2; }
    }
    __syncthreads();
    if (t < 32) {
        const int g2 = t >> 3, rr2 = t & 7;
        const int row = row0 + g2 * 8 + rr2;
        g_f1[row] = red1[rr2][g2][0] + red1[rr2][g2][1];
        g_f2[row] = red2[rr2][g2][0] + red2[rr2][g2][1];
    }
}

// =====================================================================
// Kernel B: expe = fp16(exp(e-8)) (0 where masked) + partial column sums.
// 8 columns/thread: 2x int4 + 2x float4 loads, one uint4 fp16 store.
// grid (1, BB, SPLIT) x 256 threads; 64 rows per block.
// =====================================================================
__global__ __launch_bounds__(256) void k_colsum(const int* __restrict__ adj,
                                                const float* __restrict__ nt)
{
    const int j = threadIdx.x * 8;
    const int b = blockIdx.y;
    const int i0 = blockIdx.z * (NN / SPLIT);

    const float4 f2a = *(const float4*)(g_f2 + b * NN + j);
    const float4 f2b = *(const float4*)(g_f2 + b * NN + j + 4);
    const float* f1p = g_f1 + b * NN + i0;
    size_t base = ((size_t)(b * NN + i0)) * NN + j;

    float s[8] = {0.f, 0.f, 0.f, 0.f, 0.f, 0.f, 0.f, 0.f};
#pragma unroll 4
    for (int ii = 0; ii < NN / SPLIT; ++ii) {
        const int4   av0 = *(const int4*)(adj + base);
        const int4   av1 = *(const int4*)(adj + base + 4);
        const float4 nt0 = *(const float4*)(nt + base);
        const float4 nt1 = *(const float4*)(nt + base + 4);
        const float  f1i = __ldg(&f1p[ii]);

        float p[8] = {0.f, 0.f, 0.f, 0.f, 0.f, 0.f, 0.f, 0.f};
        if (av0.x > 0) { const float x = f1i + f2a.x; p[0] = __expf((x > 0.f ? x : LALPHA * x) * nt0.x - EBIAS); }
        if (av0.y > 0) { const float x = f1i + f2a.y; p[1] = __expf((x > 0.f ? x : LALPHA * x) * nt0.y - EBIAS); }
        if (av0.z > 0) { const float x = f1i + f2a.z; p[2] = __expf((x > 0.f ? x : LALPHA * x) * nt0.z - EBIAS); }
        if (av0.w > 0) { const float x = f1i + f2a.w; p[3] = __expf((x > 0.f ? x : LALPHA * x) * nt0.w - EBIAS); }
        if (av1.x > 0) { const float x = f1i + f2b.x; p[4] = __expf((x > 0.f ? x : LALPHA * x) * nt1.x - EBIAS); }
        if (av1.y > 0) { const float x = f1i + f2b.y; p[5] = __expf((x > 0.f ? x : LALPHA * x) * nt1.y - EBIAS); }
        if (av1.z > 0) { const float x = f1i + f2b.z; p[6] = __expf((x > 0.f ? x : LALPHA * x) * nt1.z - EBIAS); }
        if (av1.w > 0) { const float x = f1i + f2b.w; p[7] = __expf((x > 0.f ? x : LALPHA * x) * nt1.w - EBIAS); }

        const __half2 h0 = __floats2half2_rn(p[0], p[1]);
        const __half2 h1 = __floats2half2_rn(p[2], p[3]);
        const __half2 h2 = __floats2half2_rn(p[4], p[5]);
        const __half2 h3 = __floats2half2_rn(p[6], p[7]);
        uint4 st;
        st.x = *(const unsigned int*)&h0;
        st.y = *(const unsigned int*)&h1;
        st.z = *(const unsigned int*)&h2;
        st.w = *(const unsigned int*)&h3;
        *(uint4*)(g_expe + base) = st;

#pragma unroll
        for (int k = 0; k < 8; ++k) s[k] += p[k];   // pre-round sums (stat. identical)
        base += NN;
    }
    float* pp = g_part + ((size_t)blockIdx.z * BB + b) * NN + j;
    *(float4*)pp       = make_float4(s[0], s[1], s[2], s[3]);
    *(float4*)(pp + 4) = make_float4(s[4], s[5], s[6], s[7]);
}

// =====================================================================
// Combine partials -> inv; WhLh = fp16(WhL * inv). 16 cols per block.
// =====================================================================
__global__ __launch_bounds__(256) void k_comb()
{
    __shared__ float sinv[16];
    const int t = threadIdx.x;
    const int col0 = blockIdx.x * 16;

    if (t < 16) {
        const int c = col0 + t;
        float s = 0.f;
#pragma unroll
        for (int k = 0; k < SPLIT; ++k) s += g_part[k * (BB * NN) + c];
        sinv[t] = 1.0f / s;
    }
    __syncthreads();

    const int cc = t >> 4;
    const int o4 = t & 15;
    const float inv = sinv[cc];
    const float4 v = ((const float4*)g_WhL)[(size_t)(col0 + cc) * 16 + o4];
    const __half2 h0 = __floats2half2_rn(v.x * inv, v.y * inv);
    const __half2 h1 = __floats2half2_rn(v.z * inv, v.w * inv);
    uint2 u;
    u.x = *(const unsigned int*)&h0;
    u.y = *(const unsigned int*)&h1;
    ((uint2*)g_WhLh)[(size_t)(col0 + cc) * 16 + o4] = u;
}

// =====================================================================
// Kernel C: HMMA partial over a K-slice of 512.
// Block: 64 i x 64 o; 8 chunks of K=64, double-buffered smem.
// grid (NN/64, BB, SPLITK) = 1024 blocks x 256 threads.
// =====================================================================
#define PITCH 72   // halves; 144B row pitch -> conflict-free ldmatrix/STS
#define KSL (NN / SPLITK)

__global__ __launch_bounds__(256) void k_attn()
{
    __shared__ __half Ps[2][64 * PITCH];
    __shared__ __half Ws[2][64 * PITCH];

    const int t = threadIdx.x;
    const int lane = t & 31;
    const int warp = t >> 5;
    const int wr = warp >> 1;          // 0..3
    const int wc = warp & 1;           // 0..1
    const int b  = blockIdx.y;
    const int i0 = blockIdx.x * 64;
    const int ks = blockIdx.z;

    const int r0 = t >> 3, c0 = t & 7;
    const int r1 = r0 + 32;
    const __half* Pg = g_expe + ((size_t)(b * NN + i0)) * NN + ks * KSL;
    const __half* Wg = g_WhLh + ((size_t)(b * NN + ks * KSL)) * FOUT;

    float d[4][4];
#pragma unroll
    for (int n = 0; n < 4; ++n)
#pragma unroll
        for (int k = 0; k < 4; ++k) d[n][k] = 0.f;

    const uint32_t aBase = smem_u32(&Ps[0][(wr * 16 + (lane & 15)) * PITCH + (lane >> 4) * 8]);
    const uint32_t bBase = smem_u32(&Ws[0][(lane & 15) * PITCH + wc * 32 + (lane >> 4) * 8]);
    const uint32_t bufStride = 64 * PITCH * sizeof(__half);

    // ---- preload chunk 0 ----
    uint4 pa = *(const uint4*)(Pg + (size_t)r0 * NN + c0 * 8);
    uint4 pb = *(const uint4*)(Pg + (size_t)r1 * NN + c0 * 8);
    uint4 wa = *(const uint4*)(Wg + (size_t)r0 * FOUT + c0 * 8);
    uint4 wb = *(const uint4*)(Wg + (size_t)r1 * FOUT + c0 * 8);
    *(uint4*)&Ps[0][r0 * PITCH + c0 * 8] = pa;
    *(uint4*)&Ps[0][r1 * PITCH + c0 * 8] = pb;
    *(uint4*)&Ws[0][r0 * PITCH + c0 * 8] = wa;
    *(uint4*)&Ws[0][r1 * PITCH + c0 * 8] = wb;
    __syncthreads();

    for (int ck = 0; ck < KSL / 64; ++ck) {
        const int buf = ck & 1;

        if (ck < KSL / 64 - 1) {
            const int k0 = (ck + 1) * 64;
            pa = *(const uint4*)(Pg + (size_t)r0 * NN + k0 + c0 * 8);
            pb = *(const uint4*)(Pg + (size_t)r1 * NN + k0 + c0 * 8);
            wa = *(const uint4*)(Wg + (size_t)(k0 + r0) * FOUT + c0 * 8);
            wb = *(const uint4*)(Wg + (size_t)(k0 + r1) * FOUT + c0 * 8);
        }

        const uint32_t aB = aBase + buf * bufStride;
        const uint32_t bB = bBase + buf * bufStride;
#pragma unroll
        for (int kss = 0; kss < 4; ++kss) {
            uint32_t a0, a1, a2, a3;
            asm volatile("ldmatrix.sync.aligned.m8n8.x4.shared.b16 {%0,%1,%2,%3}, [%4];"
                         : "=r"(a0), "=r"(a1), "=r"(a2), "=r"(a3)
                         : "r"(aB + kss * 16 * 2));
#pragma unroll
            for (int np = 0; np < 2; ++np) {
                uint32_t b0, b1, b2, b3;
                asm volatile("ldmatrix.sync.aligned.m8n8.x4.trans.shared.b16 {%0,%1,%2,%3}, [%4];"
                             : "=r"(b0), "=r"(b1), "=r"(b2), "=r"(b3)
                             : "r"(bB + (kss * 16 * PITCH + np * 16) * 2));
                asm volatile("mma.sync.aligned.m16n8k16.row.col.f32.f16.f16.f32 "
                             "{%0,%1,%2,%3}, {%4,%5,%6,%7}, {%8,%9}, {%0,%1,%2,%3};"
                             : "+f"(d[np*2][0]), "+f"(d[np*2][1]), "+f"(d[np*2][2]), "+f"(d[np*2][3])
                             : "r"(a0), "r"(a1), "r"(a2), "r"(a3), "r"(b0), "r"(b1));
                asm volatile("mma.sync.aligned.m16n8k16.row.col.f32.f16.f16.f32 "
                             "{%0,%1,%2,%3}, {%4,%5,%6,%7}, {%8,%9}, {%0,%1,%2,%3};"
                             : "+f"(d[np*2+1][0]), "+f"(d[np*2+1][1]), "+f"(d[np*2+1][2]), "+f"(d[np*2+1][3])
                             : "r"(a0), "r"(a1), "r"(a2), "r"(a3), "r"(b2), "r"(b3));
            }
        }

        if (ck < KSL / 64 - 1) {
            const int nb = buf ^ 1;
            __syncthreads();   // all warps done reading buf^1 from 2 chunks ago
            *(uint4*)&Ps[nb][r0 * PITCH + c0 * 8] = pa;
            *(uint4*)&Ps[nb][r1 * PITCH + c0 * 8] = pb;
            *(uint4*)&Ws[nb][r0 * PITCH + c0 * 8] = wa;
            *(uint4*)&Ws[nb][r1 * PITCH + c0 * 8] = wb;
            __syncthreads();
        }
    }

    // ---- store K-slice partials ----
    const int orow = i0 + wr * 16 + (lane >> 2);
    const int ocol = wc * 32 + (lane & 3) * 2;
    float* obase = g_pout + (((size_t)ks * BB + b) * NN + orow) * FOUT + ocol;
#pragma unroll
    for (int nt4 = 0; nt4 < 4; ++nt4) {
        *(float2*)(obase + nt4 * 8) = make_float2(d[nt4][0], d[nt4][1]);
        *(float2*)(obase + (size_t)8 * FOUT + nt4 * 8) = make_float2(d[nt4][2], d[nt4][3]);
    }
}

// =====================================================================
// Combine K-split partials + relu -> out
// =====================================================================
__global__ __launch_bounds__(256) void k_out(float* __restrict__ out)
{
    const int i4 = blockIdx.x * 256 + threadIdx.x;
    const size_t stride4 = (size_t)BB * NN * FOUT / 4;
    float4 s = ((const float4*)g_pout)[i4];
#pragma unroll
    for (int k = 1; k < SPLITK; ++k) {
        const float4 v = ((const float4*)g_pout)[k * stride4 + i4];
        s.x += v.x; s.y += v.y; s.z += v.z; s.w += v.w;
    }
    s.x = fmaxf(s.x, 0.f); s.y = fmaxf(s.y, 0.f);
    s.z = fmaxf(s.z, 0.f); s.w = fmaxf(s.w, 0.f);
    ((float4*)out)[i4] = s;
}

// =====================================================================
extern "C" void kernel_launch(void* const* d_in, const int* in_sizes, int n_in,
                              void* d_out, int out_size)
{
    const float* h     = (const float*)d_in[0];
    const int*   adj   = (const int*)  d_in[1];
    const float* level = (const float*)d_in[2];
    const float* nt    = (const float*)d_in[3];
    const float* W     = (const float*)d_in[4];
    const float* a     = (const float*)d_in[5];
    float* out = (float*)d_out;

    k_proj<<<(BB * NN) / 32, 256>>>(h, W, a, level);
    dim3 gb(1, BB, SPLIT);
    k_colsum<<<gb, 256>>>(adj, nt);
    k_comb<<<(BB * NN) / 16, 256>>>();
    dim3 ga(NN / 64, BB, SPLITK);
    k_attn<<<ga, 256>>>();
    k_out<<<(BB * NN * FOUT / 4) / 256, 256>>>(out);
}

// round 9
// speedup vs baseline: 1.2059x; 1.2059x over previous
#include <cuda_runtime.h>
#include <cuda_fp16.h>
#include <cstdint>

#define BB 8
#define NN 2048
#define FIN 256
#define FOUT 64
#define LALPHA 0.2f
#define SPLIT 32

// ---- scratch (device globals; no allocation) ----
__device__ float  g_WhL[BB * NN * FOUT];           // Wh*level fp32 (4 MB)
__device__ __half g_WhLh[BB * NN * FOUT];          // scaled fp16 (2 MB)
__device__ float  g_f1[BB * NN];
__device__ float  g_f2[BB * NN];
__device__ float  g_part[SPLIT * BB * NN];
__device__ __half g_expe[(size_t)BB * NN * NN];    // exp(e-8) fp16, masked->0 (67 MB)

static __device__ __forceinline__ uint32_t smem_u32(const void* p) {
    return (uint32_t)__cvta_generic_to_shared(p);
}

// exp(x - 8) on the FMA/ALU pipes (no MUFU). |rel err| ~4e-5.
static __device__ __forceinline__ float fast_exp_m8(float x) {
    const float y = fmaf(x, 1.4426950408889634f, -11.541560327111708f); // x*log2e - 8*log2e
    const float z = y + 12582912.0f;            // round(y) in low mantissa (0x4B400000)
    const int   k = __float_as_int(z) - 0x4B400000;
    const float r = y - (z - 12582912.0f);      // r in [-0.5, 0.5]
    float p = fmaf(r, 0.009618129107628f, 0.055504108664822f);
    p = fmaf(r, p, 0.240226506959101f);
    p = fmaf(r, p, 0.693147180559945f);
    p = fmaf(r, p, 1.0f);
    return __int_as_float(__float_as_int(p) + (k << 23));
}

// =====================================================================
// Kernel A: Wh = h@W, WhL = Wh*level, f1 = Wh@a1, f2 = Wh@a2
// =====================================================================
__global__ __launch_bounds__(256) void k_proj(const float* __restrict__ h,
                                              const float* __restrict__ W,
                                              const float* __restrict__ a,
                                              const float* __restrict__ level)
{
    __shared__ float sh_h[32 * FIN];
    __shared__ float red1[8][4][2];
    __shared__ float red2[8][4][2];

    const int t = threadIdx.x;
    const int row0 = blockIdx.x * 32;

    const float4* hg = (const float4*)(h + (size_t)row0 * FIN);
    float4* hs = (float4*)sh_h;
#pragma unroll
    for (int k = 0; k < 8; ++k) hs[t + k * 256] = hg[t + k * 256];
    __syncthreads();

    const int o = t & 63;
    const int g = t >> 6;
    const float a1o = a[o];
    const float a2o = a[FOUT + o];

    float acc[8] = {0.f, 0.f, 0.f, 0.f, 0.f, 0.f, 0.f, 0.f};

#pragma unroll 4
    for (int f4 = 0; f4 < FIN / 4; ++f4) {
        const float w0 = __ldg(&W[(f4 * 4 + 0) * FOUT + o]);
        const float w1 = __ldg(&W[(f4 * 4 + 1) * FOUT + o]);
        const float w2 = __ldg(&W[(f4 * 4 + 2) * FOUT + o]);
        const float w3 = __ldg(&W[(f4 * 4 + 3) * FOUT + o]);
#pragma unroll
        for (int rr = 0; rr < 8; ++rr) {
            const float4 hv = *(const float4*)&sh_h[(g * 8 + rr) * FIN + f4 * 4];
            acc[rr] = fmaf(hv.x, w0, acc[rr]);
            acc[rr] = fmaf(hv.y, w1, acc[rr]);
            acc[rr] = fmaf(hv.z, w2, acc[rr]);
            acc[rr] = fmaf(hv.w, w3, acc[rr]);
        }
    }

    const int lane = t & 31;
    const int half = (t >> 5) & 1;
#pragma unroll
    for (int rr = 0; rr < 8; ++rr) {
        const int row = row0 + g * 8 + rr;
        const float lev = __ldg(&level[row]);
        g_WhL[(size_t)row * FOUT + o] = acc[rr] * lev;
        float v1 = acc[rr] * a1o;
        float v2 = acc[rr] * a2o;
#pragma unroll
        for (int off = 16; off; off >>= 1) {
            v1 += __shfl_down_sync(0xffffffffu, v1, off);
            v2 += __shfl_down_sync(0xffffffffu, v2, off);
        }
        if (lane == 0) { red1[rr][g][half] = v1; red2[rr][g][half] = v2; }
    }
    __syncthreads();
    if (t < 32) {
        const int g2 = t >> 3, rr2 = t & 7;
        const int row = row0 + g2 * 8 + rr2;
        g_f1[row] = red1[rr2][g2][0] + red1[rr2][g2][1];
        g_f2[row] = red2[rr2][g2][0] + red2[rr2][g2][1];
    }
}

// =====================================================================
// Kernel B: expe = fp16(exp(e-8)) (0 where masked) + partial column sums.
// Branchless poly exp (FMA pipe), 4 cols/thread, coalesced int4/float4.
// grid (NN/1024, BB, SPLIT) = 512 blocks x 256 threads; 64 rows/block.
// =====================================================================
__global__ __launch_bounds__(256) void k_colsum(const int* __restrict__ adj,
                                                const float* __restrict__ nt)
{
    const int j = (blockIdx.x * 256 + threadIdx.x) * 4;
    const int b = blockIdx.y;
    const int i0 = blockIdx.z * (NN / SPLIT);

    const float4 f2v = *(const float4*)(g_f2 + b * NN + j);
    const float* f1p = g_f1 + b * NN + i0;
    size_t base = ((size_t)(b * NN + i0)) * NN + j;

    float s0 = 0.f, s1 = 0.f, s2 = 0.f, s3 = 0.f;
#pragma unroll 4
    for (int ii = 0; ii < NN / SPLIT; ++ii) {
        const int4   av  = *(const int4*)(adj + base);
        const float4 ntv = *(const float4*)(nt + base);
        const float  f1i = __ldg(&f1p[ii]);

        const float x0 = f1i + f2v.x;
        const float x1 = f1i + f2v.y;
        const float x2 = f1i + f2v.z;
        const float x3 = f1i + f2v.w;
        const float e0 = (x0 > 0.f ? x0 : LALPHA * x0) * ntv.x;
        const float e1 = (x1 > 0.f ? x1 : LALPHA * x1) * ntv.y;
        const float e2 = (x2 > 0.f ? x2 : LALPHA * x2) * ntv.z;
        const float e3 = (x3 > 0.f ? x3 : LALPHA * x3) * ntv.w;
        const float p0 = av.x > 0 ? fast_exp_m8(e0) : 0.f;
        const float p1 = av.y > 0 ? fast_exp_m8(e1) : 0.f;
        const float p2 = av.z > 0 ? fast_exp_m8(e2) : 0.f;
        const float p3 = av.w > 0 ? fast_exp_m8(e3) : 0.f;

        const __half2 h01 = __floats2half2_rn(p0, p1);
        const __half2 h23 = __floats2half2_rn(p2, p3);
        uint2 st;
        st.x = *(const unsigned int*)&h01;
        st.y = *(const unsigned int*)&h23;
        *(uint2*)(g_expe + base) = st;

        s0 += p0; s1 += p1; s2 += p2; s3 += p3;
        base += NN;
    }
    float* pp = g_part + ((size_t)blockIdx.z * BB + b) * NN + j;
    *(float4*)pp = make_float4(s0, s1, s2, s3);
}

// =====================================================================
// Combine partials -> inv; WhLh = fp16(WhL * inv). 16 cols per block.
// =====================================================================
__global__ __launch_bounds__(256) void k_comb()
{
    __shared__ float sinv[16];
    const int t = threadIdx.x;
    const int col0 = blockIdx.x * 16;

    if (t < 16) {
        const int c = col0 + t;
        float s = 0.f;
#pragma unroll
        for (int k = 0; k < SPLIT; ++k) s += g_part[k * (BB * NN) + c];
        sinv[t] = 1.0f / s;
    }
    __syncthreads();

    const int cc = t >> 4;
    const int o4 = t & 15;
    const float inv = sinv[cc];
    const float4 v = ((const float4*)g_WhL)[(size_t)(col0 + cc) * 16 + o4];
    const __half2 h0 = __floats2half2_rn(v.x * inv, v.y * inv);
    const __half2 h1 = __floats2half2_rn(v.z * inv, v.w * inv);
    uint2 u;
    u.x = *(const unsigned int*)&h0;
    u.y = *(const unsigned int*)&h1;
    ((uint2*)g_WhLh)[(size_t)(col0 + cc) * 16 + o4] = u;
}

// =====================================================================
// Kernel C: out[b,i,:] = relu( P[b,i,:] @ WhLh[b,:,:] ) via HMMA.
// Block: 64 i x 64 o, K=2048 in 64-chunks, double-buffered smem.
// grid (NN/64, BB) = 256 blocks x 256 threads.
// =====================================================================
#define PITCH 72   // halves; 144B row pitch -> conflict-free ldmatrix/STS

__global__ __launch_bounds__(256) void k_attn(float* __restrict__ out)
{
    __shared__ __half Ps[2][64 * PITCH];
    __shared__ __half Ws[2][64 * PITCH];

    const int t = threadIdx.x;
    const int lane = t & 31;
    const int warp = t >> 5;
    const int wr = warp >> 1;          // 0..3
    const int wc = warp & 1;           // 0..1
    const int b  = blockIdx.y;
    const int i0 = blockIdx.x * 64;

    const int r0 = t >> 3, c0 = t & 7;
    const int r1 = r0 + 32;
    const __half* Pg = g_expe + ((size_t)(b * NN + i0)) * NN;
    const __half* Wg = g_WhLh + (size_t)b * NN * FOUT;

    float d[4][4];
#pragma unroll
    for (int n = 0; n < 4; ++n)
#pragma unroll
        for (int k = 0; k < 4; ++k) d[n][k] = 0.f;

    const uint32_t aBase = smem_u32(&Ps[0][(wr * 16 + (lane & 15)) * PITCH + (lane >> 4) * 8]);
    const uint32_t bBase = smem_u32(&Ws[0][(lane & 15) * PITCH + wc * 32 + (lane >> 4) * 8]);
    const uint32_t bufStride = 64 * PITCH * sizeof(__half);

    // ---- preload chunk 0 ----
    uint4 pa = *(const uint4*)(Pg + (size_t)r0 * NN + c0 * 8);
    uint4 pb = *(const uint4*)(Pg + (size_t)r1 * NN + c0 * 8);
    uint4 wa = *(const uint4*)(Wg + (size_t)r0 * FOUT + c0 * 8);
    uint4 wb = *(const uint4*)(Wg + (size_t)r1 * FOUT + c0 * 8);
    *(uint4*)&Ps[0][r0 * PITCH + c0 * 8] = pa;
    *(uint4*)&Ps[0][r1 * PITCH + c0 * 8] = pb;
    *(uint4*)&Ws[0][r0 * PITCH + c0 * 8] = wa;
    *(uint4*)&Ws[0][r1 * PITCH + c0 * 8] = wb;
    __syncthreads();

    for (int ck = 0; ck < NN / 64; ++ck) {
        const int buf = ck & 1;

        if (ck < NN / 64 - 1) {
            const int k0 = (ck + 1) * 64;
            pa = *(const uint4*)(Pg + (size_t)r0 * NN + k0 + c0 * 8);
            pb = *(const uint4*)(Pg + (size_t)r1 * NN + k0 + c0 * 8);
            wa = *(const uint4*)(Wg + (size_t)(k0 + r0) * FOUT + c0 * 8);
            wb = *(const uint4*)(Wg + (size_t)(k0 + r1) * FOUT + c0 * 8);
        }

        const uint32_t aB = aBase + buf * bufStride;
        const uint32_t bB = bBase + buf * bufStride;
#pragma unroll
        for (int ks = 0; ks < 4; ++ks) {
            uint32_t a0, a1, a2, a3;
            asm volatile("ldmatrix.sync.aligned.m8n8.x4.shared.b16 {%0,%1,%2,%3}, [%4];"
                         : "=r"(a0), "=r"(a1), "=r"(a2), "=r"(a3)
                         : "r"(aB + ks * 16 * 2));
#pragma unroll
            for (int np = 0; np < 2; ++np) {
                uint32_t b0, b1, b2, b3;
                asm volatile("ldmatrix.sync.aligned.m8n8.x4.trans.shared.b16 {%0,%1,%2,%3}, [%4];"
                             : "=r"(b0), "=r"(b1), "=r"(b2), "=r"(b3)
                             : "r"(bB + (ks * 16 * PITCH + np * 16) * 2));
                asm volatile("mma.sync.aligned.m16n8k16.row.col.f32.f16.f16.f32 "
                             "{%0,%1,%2,%3}, {%4,%5,%6,%7}, {%8,%9}, {%0,%1,%2,%3};"
                             : "+f"(d[np*2][0]), "+f"(d[np*2][1]), "+f"(d[np*2][2]), "+f"(d[np*2][3])
                             : "r"(a0), "r"(a1), "r"(a2), "r"(a3), "r"(b0), "r"(b1));
                asm volatile("mma.sync.aligned.m16n8k16.row.col.f32.f16.f16.f32 "
                             "{%0,%1,%2,%3}, {%4,%5,%6,%7}, {%8,%9}, {%0,%1,%2,%3};"
                             : "+f"(d[np*2+1][0]), "+f"(d[np*2+1][1]), "+f"(d[np*2+1][2]), "+f"(d[np*2+1][3])
                             : "r"(a0), "r"(a1), "r"(a2), "r"(a3), "r"(b2), "r"(b3));
            }
        }

        if (ck < NN / 64 - 1) {
            const int nb = buf ^ 1;
            *(uint4*)&Ps[nb][r0 * PITCH + c0 * 8] = pa;
            *(uint4*)&Ps[nb][r1 * PITCH + c0 * 8] = pb;
            *(uint4*)&Ws[nb][r0 * PITCH + c0 * 8] = wa;
            *(uint4*)&Ws[nb][r1 * PITCH + c0 * 8] = wb;
            __syncthreads();
        }
    }

    // ---- epilogue: relu + store ----
    const int orow = i0 + wr * 16 + (lane >> 2);
    const int ocol = wc * 32 + (lane & 3) * 2;
    float* obase = out + ((size_t)(b * NN + orow)) * FOUT + ocol;
#pragma unroll
    for (int nt4 = 0; nt4 < 4; ++nt4) {
        float2 v0, v1;
        v0.x = fmaxf(d[nt4][0], 0.f); v0.y = fmaxf(d[nt4][1], 0.f);
        v1.x = fmaxf(d[nt4][2], 0.f); v1.y = fmaxf(d[nt4][3], 0.f);
        *(float2*)(obase + nt4 * 8) = v0;
        *(float2*)(obase + (size_t)8 * FOUT + nt4 * 8) = v1;
    }
}

// =====================================================================
extern "C" void kernel_launch(void* const* d_in, const int* in_sizes, int n_in,
                              void* d_out, int out_size)
{
    const float* h     = (const float*)d_in[0];
    const int*   adj   = (const int*)  d_in[1];
    const float* level = (const float*)d_in[2];
    const float* nt    = (const float*)d_in[3];
    const float* W     = (const float*)d_in[4];
    const float* a     = (const float*)d_in[5];
    float* out = (float*)d_out;

    k_proj<<<(BB * NN) / 32, 256>>>(h, W, a, level);
    dim3 gb(NN / 1024, BB, SPLIT);
    k_colsum<<<gb, 256>>>(adj, nt);
    k_comb<<<(BB * NN) / 16, 256>>>();
    dim3 ga(NN / 64, BB);
    k_attn<<<ga, 256>>>(out);
}

// round 10
// speedup vs baseline: 1.2087x; 1.0023x over previous
#include <cuda_runtime.h>
#include <cuda_fp16.h>
#include <cstdint>

#define BB 8
#define NN 2048
#define FIN 256
#define FOUT 64
#define LALPHA 0.2f
#define SPLIT 64

// ---- scratch (device globals; no allocation) ----
__device__ float  g_WhL[BB * NN * FOUT];           // Wh*level fp32 (4 MB)
__device__ __half g_WhLh[BB * NN * FOUT];          // scaled fp16 (2 MB)
__device__ float  g_f1[BB * NN];
__device__ float  g_f2[BB * NN];
__device__ float  g_part[SPLIT * BB * NN];
__device__ __half g_expe[(size_t)BB * NN * NN];    // exp(e-8) fp16, masked->0 (67 MB)

static __device__ __forceinline__ uint32_t smem_u32(const void* p) {
    return (uint32_t)__cvta_generic_to_shared(p);
}

static __device__ __forceinline__ void cp16(uint32_t dst, const void* src) {
    asm volatile("cp.async.cg.shared.global [%0], [%1], 16;" :: "r"(dst), "l"(src));
}
static __device__ __forceinline__ void cp_commit() {
    asm volatile("cp.async.commit_group;" ::: "memory");
}
static __device__ __forceinline__ void cp_wait0() {
    asm volatile("cp.async.wait_group 0;" ::: "memory");
}

// exp(x - 8) on the FMA/ALU pipes (no MUFU). |rel err| ~4e-5.
static __device__ __forceinline__ float fast_exp_m8(float x) {
    const float y = fmaf(x, 1.4426950408889634f, -11.541560327111708f);
    const float z = y + 12582912.0f;
    const int   k = __float_as_int(z) - 0x4B400000;
    const float r = y - (z - 12582912.0f);
    float p = fmaf(r, 0.009618129107628f, 0.055504108664822f);
    p = fmaf(r, p, 0.240226506959101f);
    p = fmaf(r, p, 0.693147180559945f);
    p = fmaf(r, p, 1.0f);
    return __int_as_float(__float_as_int(p) + (k << 23));
}

// =====================================================================
// Kernel A: Wh = h@W, WhL = Wh*level, f1 = Wh@a1, f2 = Wh@a2
// =====================================================================
__global__ __launch_bounds__(256) void k_proj(const float* __restrict__ h,
                                              const float* __restrict__ W,
                                              const float* __restrict__ a,
                                              const float* __restrict__ level)
{
    __shared__ float sh_h[32 * FIN];
    __shared__ float red1[8][4][2];
    __shared__ float red2[8][4][2];

    const int t = threadIdx.x;
    const int row0 = blockIdx.x * 32;

    const float4* hg = (const float4*)(h + (size_t)row0 * FIN);
    float4* hs = (float4*)sh_h;
#pragma unroll
    for (int k = 0; k < 8; ++k) hs[t + k * 256] = hg[t + k * 256];
    __syncthreads();

    const int o = t & 63;
    const int g = t >> 6;
    const float a1o = a[o];
    const float a2o = a[FOUT + o];

    float acc[8] = {0.f, 0.f, 0.f, 0.f, 0.f, 0.f, 0.f, 0.f};

#pragma unroll 4
    for (int f4 = 0; f4 < FIN / 4; ++f4) {
        const float w0 = __ldg(&W[(f4 * 4 + 0) * FOUT + o]);
        const float w1 = __ldg(&W[(f4 * 4 + 1) * FOUT + o]);
        const float w2 = __ldg(&W[(f4 * 4 + 2) * FOUT + o]);
        const float w3 = __ldg(&W[(f4 * 4 + 3) * FOUT + o]);
#pragma unroll
        for (int rr = 0; rr < 8; ++rr) {
            const float4 hv = *(const float4*)&sh_h[(g * 8 + rr) * FIN + f4 * 4];
            acc[rr] = fmaf(hv.x, w0, acc[rr]);
            acc[rr] = fmaf(hv.y, w1, acc[rr]);
            acc[rr] = fmaf(hv.z, w2, acc[rr]);
            acc[rr] = fmaf(hv.w, w3, acc[rr]);
        }
    }

    const int lane = t & 31;
    const int half = (t >> 5) & 1;
#pragma unroll
    for (int rr = 0; rr < 8; ++rr) {
        const int row = row0 + g * 8 + rr;
        const float lev = __ldg(&level[row]);
        g_WhL[(size_t)row * FOUT + o] = acc[rr] * lev;
        float v1 = acc[rr] * a1o;
        float v2 = acc[rr] * a2o;
#pragma unroll
        for (int off = 16; off; off >>= 1) {
            v1 += __shfl_down_sync(0xffffffffu, v1, off);
            v2 += __shfl_down_sync(0xffffffffu, v2, off);
        }
        if (lane == 0) { red1[rr][g][half] = v1; red2[rr][g][half] = v2; }
    }
    __syncthreads();
    if (t < 32) {
        const int g2 = t >> 3, rr2 = t & 7;
        const int row = row0 + g2 * 8 + rr2;
        g_f1[row] = red1[rr2][g2][0] + red1[rr2][g2][1];
        g_f2[row] = red2[rr2][g2][0] + red2[rr2][g2][1];
    }
}

// =====================================================================
// Kernel B: expe = fp16(exp(e-8)) (0 where masked) + partial column sums.
// adj/nt read with evict-first (__ldcs) so g_expe stays L2-resident.
// grid (NN/1024, BB, SPLIT) = 1024 blocks x 256 threads; 32 rows/block.
// =====================================================================
__global__ __launch_bounds__(256) void k_colsum(const int* __restrict__ adj,
                                                const float* __restrict__ nt)
{
    const int j = (blockIdx.x * 256 + threadIdx.x) * 4;
    const int b = blockIdx.y;
    const int i0 = blockIdx.z * (NN / SPLIT);

    const float4 f2v = *(const float4*)(g_f2 + b * NN + j);
    const float* f1p = g_f1 + b * NN + i0;
    size_t base = ((size_t)(b * NN + i0)) * NN + j;

    float s0 = 0.f, s1 = 0.f, s2 = 0.f, s3 = 0.f;
#pragma unroll 4
    for (int ii = 0; ii < NN / SPLIT; ++ii) {
        const int4   av  = __ldcs((const int4*)(adj + base));
        const float4 ntv = __ldcs((const float4*)(nt + base));
        const float  f1i = __ldg(&f1p[ii]);

        const float x0 = f1i + f2v.x;
        const float x1 = f1i + f2v.y;
        const float x2 = f1i + f2v.z;
        const float x3 = f1i + f2v.w;
        const float e0 = (x0 > 0.f ? x0 : LALPHA * x0) * ntv.x;
        const float e1 = (x1 > 0.f ? x1 : LALPHA * x1) * ntv.y;
        const float e2 = (x2 > 0.f ? x2 : LALPHA * x2) * ntv.z;
        const float e3 = (x3 > 0.f ? x3 : LALPHA * x3) * ntv.w;
        const float p0 = av.x > 0 ? fast_exp_m8(e0) : 0.f;
        const float p1 = av.y > 0 ? fast_exp_m8(e1) : 0.f;
        const float p2 = av.z > 0 ? fast_exp_m8(e2) : 0.f;
        const float p3 = av.w > 0 ? fast_exp_m8(e3) : 0.f;

        const __half2 h01 = __floats2half2_rn(p0, p1);
        const __half2 h23 = __floats2half2_rn(p2, p3);
        uint2 st;
        st.x = *(const unsigned int*)&h01;
        st.y = *(const unsigned int*)&h23;
        *(uint2*)(g_expe + base) = st;

        s0 += p0; s1 += p1; s2 += p2; s3 += p3;
        base += NN;
    }
    float* pp = g_part + ((size_t)blockIdx.z * BB + b) * NN + j;
    *(float4*)pp = make_float4(s0, s1, s2, s3);
}

// =====================================================================
// Combine partials -> inv; WhLh = fp16(WhL * inv). 16 cols per block.
// =====================================================================
__global__ __launch_bounds__(256) void k_comb()
{
    __shared__ float sinv[16];
    const int t = threadIdx.x;
    const int col0 = blockIdx.x * 16;

    if (t < 16) {
        const int c = col0 + t;
        float s = 0.f;
#pragma unroll
        for (int k = 0; k < SPLIT; ++k) s += g_part[k * (BB * NN) + c];
        sinv[t] = 1.0f / s;
    }
    __syncthreads();

    const int cc = t >> 4;
    const int o4 = t & 15;
    const float inv = sinv[cc];
    const float4 v = ((const float4*)g_WhL)[(size_t)(col0 + cc) * 16 + o4];
    const __half2 h0 = __floats2half2_rn(v.x * inv, v.y * inv);
    const __half2 h1 = __floats2half2_rn(v.z * inv, v.w * inv);
    uint2 u;
    u.x = *(const unsigned int*)&h0;
    u.y = *(const unsigned int*)&h1;
    ((uint2*)g_WhLh)[(size_t)(col0 + cc) * 16 + o4] = u;
}

// =====================================================================
// Kernel C: out[b,i,:] = relu( P[b,i,:] @ WhLh[b,:,:] ) via HMMA.
// cp.async staging (no LDG->STS round trip), double-buffered smem.
// grid (NN/64, BB) = 256 blocks x 256 threads.
// =====================================================================
#define PITCH 72   // halves; 144B row pitch -> conflict-free ldmatrix/STS

__global__ __launch_bounds__(256) void k_attn(float* __restrict__ out)
{
    __shared__ __half Ps[2][64 * PITCH];
    __shared__ __half Ws[2][64 * PITCH];

    const int t = threadIdx.x;
    const int lane = t & 31;
    const int warp = t >> 5;
    const int wr = warp >> 1;          // 0..3
    const int wc = warp & 1;           // 0..1
    const int b  = blockIdx.y;
    const int i0 = blockIdx.x * 64;

    const int r0 = t >> 3, c0 = t & 7;
    const int r1 = r0 + 32;
    const __half* Pg = g_expe + ((size_t)(b * NN + i0)) * NN;
    const __half* Wg = g_WhLh + (size_t)b * NN * FOUT;

    // smem destination addresses for this thread's 16B chunks
    const uint32_t dP0 = smem_u32(&Ps[0][r0 * PITCH + c0 * 8]);
    const uint32_t dP1 = smem_u32(&Ps[0][r1 * PITCH + c0 * 8]);
    const uint32_t dW0 = smem_u32(&Ws[0][r0 * PITCH + c0 * 8]);
    const uint32_t dW1 = smem_u32(&Ws[0][r1 * PITCH + c0 * 8]);
    const uint32_t bufStride = 64 * PITCH * sizeof(__half);

    float d[4][4];
#pragma unroll
    for (int n = 0; n < 4; ++n)
#pragma unroll
        for (int k = 0; k < 4; ++k) d[n][k] = 0.f;

    const uint32_t aBase = smem_u32(&Ps[0][(wr * 16 + (lane & 15)) * PITCH + (lane >> 4) * 8]);
    const uint32_t bBase = smem_u32(&Ws[0][(lane & 15) * PITCH + wc * 32 + (lane >> 4) * 8]);

    // ---- preload chunk 0 ----
    cp16(dP0, Pg + (size_t)r0 * NN + c0 * 8);
    cp16(dP1, Pg + (size_t)r1 * NN + c0 * 8);
    cp16(dW0, Wg + (size_t)r0 * FOUT + c0 * 8);
    cp16(dW1, Wg + (size_t)r1 * FOUT + c0 * 8);
    cp_commit();
    cp_wait0();
    __syncthreads();

    for (int ck = 0; ck < NN / 64; ++ck) {
        const int buf = ck & 1;

        // kick off async staging of the next chunk into the other buffer
        if (ck < NN / 64 - 1) {
            const int k0 = (ck + 1) * 64;
            const uint32_t nb = (buf ^ 1) * bufStride;
            cp16(dP0 + nb, Pg + (size_t)r0 * NN + k0 + c0 * 8);
            cp16(dP1 + nb, Pg + (size_t)r1 * NN + k0 + c0 * 8);
            cp16(dW0 + nb, Wg + (size_t)(k0 + r0) * FOUT + c0 * 8);
            cp16(dW1 + nb, Wg + (size_t)(k0 + r1) * FOUT + c0 * 8);
            cp_commit();
        }

        const uint32_t aB = aBase + buf * bufStride;
        const uint32_t bB = bBase + buf * bufStride;
#pragma unroll
        for (int ks = 0; ks < 4; ++ks) {
            uint32_t a0, a1, a2, a3;
            asm volatile("ldmatrix.sync.aligned.m8n8.x4.shared.b16 {%0,%1,%2,%3}, [%4];"
                         : "=r"(a0), "=r"(a1), "=r"(a2), "=r"(a3)
                         : "r"(aB + ks * 16 * 2));
#pragma unroll
            for (int np = 0; np < 2; ++np) {
                uint32_t b0, b1, b2, b3;
                asm volatile("ldmatrix.sync.aligned.m8n8.x4.trans.shared.b16 {%0,%1,%2,%3}, [%4];"
                             : "=r"(b0), "=r"(b1), "=r"(b2), "=r"(b3)
                             : "r"(bB + (ks * 16 * PITCH + np * 16) * 2));
                asm volatile("mma.sync.aligned.m16n8k16.row.col.f32.f16.f16.f32 "
                             "{%0,%1,%2,%3}, {%4,%5,%6,%7}, {%8,%9}, {%0,%1,%2,%3};"
                             : "+f"(d[np*2][0]), "+f"(d[np*2][1]), "+f"(d[np*2][2]), "+f"(d[np*2][3])
                             : "r"(a0), "r"(a1), "r"(a2), "r"(a3), "r"(b0), "r"(b1));
                asm volatile("mma.sync.aligned.m16n8k16.row.col.f32.f16.f16.f32 "
                             "{%0,%1,%2,%3}, {%4,%5,%6,%7}, {%8,%9}, {%0,%1,%2,%3};"
                             : "+f"(d[np*2+1][0]), "+f"(d[np*2+1][1]), "+f"(d[np*2+1][2]), "+f"(d[np*2+1][3])
                             : "r"(a0), "r"(a1), "r"(a2), "r"(a3), "r"(b2), "r"(b3));
            }
        }

        if (ck < NN / 64 - 1) {
            cp_wait0();        // next buffer fully staged
            __syncthreads();   // and all warps done reading current buffer
        }
    }

    // ---- epilogue: relu + store ----
    const int orow = i0 + wr * 16 + (lane >> 2);
    const int ocol = wc * 32 + (lane & 3) * 2;
    float* obase = out + ((size_t)(b * NN + orow)) * FOUT + ocol;
#pragma unroll
    for (int nt4 = 0; nt4 < 4; ++nt4) {
        float2 v0, v1;
        v0.x = fmaxf(d[nt4][0], 0.f); v0.y = fmaxf(d[nt4][1], 0.f);
        v1.x = fmaxf(d[nt4][2], 0.f); v1.y = fmaxf(d[nt4][3], 0.f);
        *(float2*)(obase + nt4 * 8) = v0;
        *(float2*)(obase + (size_t)8 * FOUT + nt4 * 8) = v1;
    }
}

// =====================================================================
extern "C" void kernel_launch(void* const* d_in, const int* in_sizes, int n_in,
                              void* d_out, int out_size)
{
    const float* h     = (const float*)d_in[0];
    const int*   adj   = (const int*)  d_in[1];
    const float* level = (const float*)d_in[2];
    const float* nt    = (const float*)d_in[3];
    const float* W     = (const float*)d_in[4];
    const float* a     = (const float*)d_in[5];
    float* out = (float*)d_out;

    k_proj<<<(BB * NN) / 32, 256>>>(h, W, a, level);
    dim3 gb(NN / 1024, BB, SPLIT);
    k_colsum<<<gb, 256>>>(adj, nt);
    k_comb<<<(BB * NN) / 16, 256>>>();
    dim3 ga(NN / 64, BB);
    k_attn<<<ga, 256>>>(out);
}